// round 12
// baseline (speedup 1.0000x reference)
#include <cuda_runtime.h>
#include <math.h>

// Problem constants (fixed by setup_inputs)
#define BB 8
#define TT 600
#define CC 8
#define FF 257
#define NTAPS 5
#define NDELAY 3
#define KC 40           // NTAPS*CC
#define EPSV 1e-10f
#define NTHREADS 256
#define NJOBS (BB*FF)   // 2056
#define NCTAS 444       // 148 SMs x occupancy 3
// valid frame count Tq = T - DELAY - TAPS + 1 = 593; u in [4, 597)

// Padded Y row: 8 leading zeros + 600 data + 10 trailing zeros = 618 float2.
// Row stride 618*8 B: 16B-aligned rows (float4 loads OK); bank offsets between
// rows = 20 mod 32 -> all 8 channel rows on distinct banks.
#define TP 618
#define TOFF 8
#define IOFF 1          // invp values at [IOFF+t] so invp[IOFF+u+3] is 16B-aligned

typedef unsigned long long u64;

// Scratch: Y and enhanced in (B,F,C,T) complex layout
__device__ float2 g_Y[(size_t)BB*FF*CC*TT];
__device__ float2 g_E[(size_t)BB*FF*CC*TT];
__device__ unsigned int g_ticket;

struct WpeSmem {
    float2 Y[CC][TP];          // 39552 B  (zero-padded both ends)
    float  invp[604];          //  2416 B  (weights during R/P; ps after)
    float2 R[KC][KC+1];        // 13120 B  (padded row; dinv lives in diag .y)
    float2 P[NTAPS][CC][CC];   //  2560 B  [k][e][d]
    float2 G[NTAPS][CC][CC];   //  2560 B  [p][d][e]
    int    job;                //  job id claimed by this CTA
};                             // ~60224 B -> 3 CTAs/SM

// ---------------- packed f32x2 helpers (sm_103a FFMA2 path) ----------------
__device__ __forceinline__ u64 pk2(float lo, float hi) {
    u64 r; asm("mov.b64 %0, {%1, %2};" : "=l"(r) : "f"(lo), "f"(hi)); return r;
}
__device__ __forceinline__ float2 upk2(u64 v) {
    float2 r; asm("mov.b64 {%0, %1}, %2;" : "=f"(r.x), "=f"(r.y) : "l"(v)); return r;
}
__device__ __forceinline__ u64 fma2(u64 a, u64 b, u64 c) {
    u64 d; asm("fma.rn.f32x2 %0, %1, %2, %3;" : "=l"(d) : "l"(a), "l"(b), "l"(c)); return d;
}
__device__ __forceinline__ u64 mul2(u64 a, u64 b) {
    u64 d; asm("mul.rn.f32x2 %0, %1, %2;" : "=l"(d) : "l"(a), "l"(b)); return d;
}
__device__ __forceinline__ float2 shfl2(float2 v, int src) {
    float2 r;
    r.x = __shfl_sync(0xffffffffu, v.x, src);
    r.y = __shfl_sync(0xffffffffu, v.y, src);
    return r;
}

// ---------------------------------------------------------------------------
// Transpose in: (B,T,C,F) real+imag planes -> g_Y (B,F,C,T) float2
// Also resets the persistent-job ticket (runs before k_wpe on the stream).
// ---------------------------------------------------------------------------
__global__ void k_transpose_in(const float* __restrict__ re,
                               const float* __restrict__ im) {
    if (blockIdx.x == 0 && blockIdx.y == 0 && blockIdx.z == 0 &&
        threadIdx.x == 0 && threadIdx.y == 0)
        g_ticket = 0u;
    __shared__ float2 tile[32][33];
    int bc = blockIdx.z;
    int b = bc / CC, c = bc % CC;
    int f0 = blockIdx.x * 32, t0 = blockIdx.y * 32;
    int tx = threadIdx.x, ty = threadIdx.y;
#pragma unroll
    for (int j = 0; j < 4; j++) {
        int t = t0 + ty + j*8, f = f0 + tx;
        if (t < TT && f < FF) {
            size_t idx = ((size_t)(b*TT + t)*CC + c)*FF + f;
            tile[ty + j*8][tx] = make_float2(re[idx], im[idx]);
        }
    }
    __syncthreads();
#pragma unroll
    for (int j = 0; j < 4; j++) {
        int f = f0 + ty + j*8, t = t0 + tx;
        if (t < TT && f < FF) {
            g_Y[((size_t)(b*FF + f)*CC + c)*TT + t] = tile[tx][ty + j*8];
        }
    }
}

// ---------------------------------------------------------------------------
// Transpose out: g_E (B,F,C,T) -> out real/imag planes (B,T,C,F), masked
// ---------------------------------------------------------------------------
__global__ void k_transpose_out(float* __restrict__ out,
                                const int* __restrict__ ilens) {
    __shared__ float2 tile[32][33];
    int bc = blockIdx.z;
    int b = bc / CC, c = bc % CC;
    int t0 = blockIdx.x * 32, f0 = blockIdx.y * 32;
    int tx = threadIdx.x, ty = threadIdx.y;
    int ilen = ilens[b];
    const size_t N = (size_t)BB*TT*CC*FF;
#pragma unroll
    for (int j = 0; j < 4; j++) {
        int f = f0 + ty + j*8, t = t0 + tx;
        if (t < TT && f < FF) {
            tile[ty + j*8][tx] = g_E[((size_t)(b*FF + f)*CC + c)*TT + t];
        }
    }
    __syncthreads();
#pragma unroll
    for (int j = 0; j < 4; j++) {
        int t = t0 + ty + j*8, f = f0 + tx;
        if (t < TT && f < FF) {
            float2 v = tile[tx][ty + j*8];
            if (t >= ilen) v = make_float2(0.f, 0.f);
            size_t idx = ((size_t)(b*TT + t)*CC + c)*FF + f;
            out[idx]     = v.x;
            out[N + idx] = v.y;
        }
    }
}

// ---------------------------------------------------------------------------
// Fused WPE: persistent CTAs; dynamic ticket over the 2056 (b,f) jobs.
// 2 iterations entirely in shared memory per job.
// ---------------------------------------------------------------------------
__global__ __launch_bounds__(NTHREADS, 3) void k_wpe() {
    extern __shared__ char smem_raw[];
    WpeSmem* s = (WpeSmem*)smem_raw;
    int tid = threadIdx.x;

    for (;;) {
        if (tid == 0) s->job = (int)atomicAdd(&g_ticket, 1u);
        __syncthreads();
        int bf = s->job;
        if (bf >= NJOBS) break;

        // Load Y rows into padded smem; zero the pads.
        const float2* Yg = g_Y + (size_t)bf * CC * TT;
#pragma unroll
        for (int c = 0; c < CC; c++)
            for (int t = tid; t < TT; t += NTHREADS)
                s->Y[c][t + TOFF] = Yg[c*TT + t];
        if (tid < CC * 18) {                 // 8 front + 10 back pads per row
            int c = tid / 18, p = tid % 18;
            int idx = (p < TOFF) ? p : (TT + p);   // 0..7 and 608..617
            s->Y[c][idx] = make_float2(0.f, 0.f);
        }
        __syncthreads();

        for (int it = 0; it < 2; it++) {
            // ---- power -> invp ----
            if (it == 0) {
                for (int t = tid; t < TT; t += NTHREADS) {
                    float sum = 0.f;
#pragma unroll
                    for (int c = 0; c < CC; c++) {
                        float2 y = s->Y[c][t + TOFF];
                        sum += y.x*y.x + y.y*y.y;
                    }
                    s->invp[t + IOFF] = 1.0f / fmaxf(sum * (1.0f / CC), EPSV);
                }
            } else {
                // invp currently holds ps (|E1|^2 sums); convert in place
                for (int t = tid; t < TT; t += NTHREADS)
                    s->invp[t + IOFF] =
                        1.0f / fmaxf(s->invp[t + IOFF] * (1.0f / CC), EPSV);
            }
            __syncthreads();

            // ---- fused R + P accumulation, single pass over full u range ----
            // Split-accumulator scheme: for conj(c)*z with weight w,
            //   accA += (w*cx,w*cx) (x) (zx,zy); accB += (w*cy,w*cy) (x) (zx,zy)
            //   re = A.lo + B.hi ;  im = A.hi - B.lo
            // R jobs: threads 0..179 = (pair d<=e [36], k [5]).
            // P jobs: threads 192..255 = ordered pair (d,e) [64].
            if (tid < 180) {
                int pair = tid / 5, k = tid % 5;
                int e = 0;
                while ((e+1)*(e+2)/2 <= pair) e++;
                int d = pair - e*(e+1)/2;            // d <= e
                u64 accA[NTAPS], accB[NTAPS];
#pragma unroll
                for (int l = 0; l < NTAPS; l++) { accA[l] = 0ull; accB[l] = 0ull; }
                u64 wep[NTAPS];                      // wep[l] = Ye[u-1-l] pack (x,y)
#pragma unroll
                for (int l = 0; l < NTAPS-1; l++) {
                    float2 y = s->Y[e][3 - l + TOFF];
                    wep[l] = pk2(y.x, y.y);
                }
                wep[NTAPS-1] = 0ull;

                for (int u = 4; u < 596; u += 4) {
                    float4 w4  = *reinterpret_cast<const float4*>(&s->invp[IOFF + u + 3]);
                    float4 yeA = *reinterpret_cast<const float4*>(&s->Y[e][u + TOFF]);
                    float4 yeB = *reinterpret_cast<const float4*>(&s->Y[e][u + 2 + TOFF]);
                    float wj[4]  = {w4.x, w4.y, w4.z, w4.w};
                    float yex[4] = {yeA.x, yeA.z, yeB.x, yeB.z};
                    float yey[4] = {yeA.y, yeA.w, yeB.y, yeB.w};
#pragma unroll
                    for (int j = 0; j < 4; j++) {
#pragma unroll
                        for (int l = NTAPS-1; l > 0; l--) wep[l] = wep[l-1];
                        wep[0] = pk2(yex[j], yey[j]);
                        float2 yd = s->Y[d][u + j - k + TOFF];
                        u64 ww = pk2(wj[j], wj[j]);
                        u64 aw = mul2(ww, pk2(yd.x, yd.x));
                        u64 bw = mul2(ww, pk2(yd.y, yd.y));
#pragma unroll
                        for (int l = 0; l < NTAPS; l++) {
                            accA[l] = fma2(aw, wep[l], accA[l]);
                            accB[l] = fma2(bw, wep[l], accB[l]);
                        }
                    }
                }
                {   // remainder u = 596
                    const int u = 596;
#pragma unroll
                    for (int l = NTAPS-1; l > 0; l--) wep[l] = wep[l-1];
                    float2 ye = s->Y[e][u + TOFF];
                    wep[0] = pk2(ye.x, ye.y);
                    float2 yd = s->Y[d][u - k + TOFF];
                    float w = s->invp[IOFF + u + 3];
                    u64 ww = pk2(w, w);
                    u64 aw = mul2(ww, pk2(yd.x, yd.x));
                    u64 bw = mul2(ww, pk2(yd.y, yd.y));
#pragma unroll
                    for (int l = 0; l < NTAPS; l++) {
                        accA[l] = fma2(aw, wep[l], accA[l]);
                        accB[l] = fma2(bw, wep[l], accB[l]);
                    }
                }
#pragma unroll
                for (int l = 0; l < NTAPS; l++) {
                    float2 A = upk2(accA[l]), B = upk2(accB[l]);
                    float2 v = make_float2(A.x + B.y, A.y - B.x);
                    s->R[k*CC + d][l*CC + e] = v;
                    if (d < e)
                        s->R[l*CC + e][k*CC + d] = make_float2(v.x, -v.y);
                }
            } else if (tid >= 192) {
                int pair = tid - 192;
                int d = pair & 7, e = pair >> 3;
                u64 accA[NTAPS], accB[NTAPS];
#pragma unroll
                for (int k = 0; k < NTAPS; k++) { accA[k] = 0ull; accB[k] = 0ull; }
                u64 dxx[NTAPS], dyy[NTAPS];          // window of Yd[u-k] broadcast packs
#pragma unroll
                for (int k = 0; k < NTAPS-1; k++) {
                    float2 yd = s->Y[d][3 - k + TOFF];
                    dxx[k] = pk2(yd.x, yd.x);
                    dyy[k] = pk2(yd.y, yd.y);
                }
                dxx[NTAPS-1] = dyy[NTAPS-1] = 0ull;

                for (int u = 4; u < 596; u += 4) {
                    float4 w4  = *reinterpret_cast<const float4*>(&s->invp[IOFF + u + 3]);
                    float4 ydA = *reinterpret_cast<const float4*>(&s->Y[d][u + TOFF]);
                    float4 ydB = *reinterpret_cast<const float4*>(&s->Y[d][u + 2 + TOFF]);
                    float wj[4]  = {w4.x, w4.y, w4.z, w4.w};
                    float ydx[4] = {ydA.x, ydA.z, ydB.x, ydB.z};
                    float ydy[4] = {ydA.y, ydA.w, ydB.y, ydB.w};
#pragma unroll
                    for (int j = 0; j < 4; j++) {
#pragma unroll
                        for (int k = NTAPS-1; k > 0; k--) { dxx[k]=dxx[k-1]; dyy[k]=dyy[k-1]; }
                        dxx[0] = pk2(ydx[j], ydx[j]);
                        dyy[0] = pk2(ydy[j], ydy[j]);
                        float2 ye = s->Y[e][u + j + 3 + TOFF];
                        u64 sv = mul2(pk2(wj[j], wj[j]), pk2(ye.x, ye.y));
#pragma unroll
                        for (int k = 0; k < NTAPS; k++) {
                            accA[k] = fma2(dxx[k], sv, accA[k]);
                            accB[k] = fma2(dyy[k], sv, accB[k]);
                        }
                    }
                }
                {   // remainder u = 596
                    const int u = 596;
#pragma unroll
                    for (int k = NTAPS-1; k > 0; k--) { dxx[k]=dxx[k-1]; dyy[k]=dyy[k-1]; }
                    float2 yd = s->Y[d][u + TOFF];
                    dxx[0] = pk2(yd.x, yd.x);
                    dyy[0] = pk2(yd.y, yd.y);
                    float2 ye = s->Y[e][u + 3 + TOFF];
                    float w = s->invp[IOFF + u + 3];
                    u64 sv = mul2(pk2(w, w), pk2(ye.x, ye.y));
#pragma unroll
                    for (int k = 0; k < NTAPS; k++) {
                        accA[k] = fma2(dxx[k], sv, accA[k]);
                        accB[k] = fma2(dyy[k], sv, accB[k]);
                    }
                }
#pragma unroll
                for (int k = 0; k < NTAPS; k++) {
                    float2 A = upk2(accA[k]), B = upk2(accB[k]);
                    s->P[k][e][d] = make_float2(A.x + B.y, A.y - B.x);
                }
            }
            __syncthreads();

            // ---- weights dead: repurpose invp as ps accumulator (zero it);
            //      regularize R diag. Both covered by LDL's first barrier. ----
            for (int t = tid; t < TT; t += NTHREADS) s->invp[t + IOFF] = 0.f;
            if (tid < KC) s->R[tid][tid].x += EPSV;

            // ---- in-place LDL^H of R: one barrier per column; dinv -> R[j][j].y
            for (int j = 0; j < KC; j++) {
                __syncthreads();                 // column j fully updated
                float djj = s->R[j][j].x;        // broadcast read
                float dinv = 1.0f / fmaxf(djj, 1e-30f);
                if (tid == 0) s->R[j][j].y = dinv;
                for (int i = j + 1 + (tid & 31); i < KC; i += 32) {
                    float2 Aij = s->R[i][j];
                    float2 Aw = make_float2(Aij.x * dinv, Aij.y * dinv);
                    for (int l = j + 1 + (tid >> 5); l <= i; l += 8) {
                        float2 Alj = s->R[l][j];
                        s->R[i][l].x -= Aw.x*Alj.x + Aw.y*Alj.y;
                        s->R[i][l].y -= Aw.y*Alj.x - Aw.x*Alj.y;
                    }
                }
            }
            __syncthreads();

            // ---- triangular solves in registers: warp e solves channel e ----
            {
                int lane = tid & 31, e = tid >> 5;
                float2 x0, x1;
                { int i = lane;      x0 = s->P[i>>3][e][i&7]; }
                if (lane < 8) { int i = lane + 32; x1 = s->P[i>>3][e][i&7]; }
                else x1 = make_float2(0.f, 0.f);
                float dinv0 = s->R[lane][lane].y;
                float dinv1 = (lane < 8) ? s->R[lane+32][lane+32].y : 0.f;

                // forward: unit-lower L y = b
                for (int j = 0; j < KC; j++) {
                    int src = j & 31;
                    float2 xj = (j < 32) ? shfl2(x0, src) : shfl2(x1, src);
                    float dj = s->R[j][j].y;
                    float2 t = make_float2(xj.x * dj, xj.y * dj);
                    if (lane > j) {
                        float2 L = s->R[lane][j];
                        x0.x -= L.x*t.x - L.y*t.y;
                        x0.y -= L.x*t.y + L.y*t.x;
                    }
                    if (lane < 8 && lane + 32 > j) {
                        float2 L = s->R[lane+32][j];
                        x1.x -= L.x*t.x - L.y*t.y;
                        x1.y -= L.x*t.y + L.y*t.x;
                    }
                }
                // z = D^{-1} y
                x0.x *= dinv0; x0.y *= dinv0;
                x1.x *= dinv1; x1.y *= dinv1;
                // backward: L^H x = z
                for (int j = KC - 1; j >= 1; j--) {
                    int src = j & 31;
                    float2 xj = (j < 32) ? shfl2(x0, src) : shfl2(x1, src);
                    if (lane < j) {
                        float2 A = s->R[j][lane];
                        x0.x -= dinv0 * (A.x*xj.x + A.y*xj.y);
                        x0.y -= dinv0 * (A.x*xj.y - A.y*xj.x);
                    }
                    if (lane < 8 && lane + 32 < j) {
                        float2 A = s->R[j][lane+32];
                        x1.x -= dinv1 * (A.x*xj.x + A.y*xj.y);
                        x1.y -= dinv1 * (A.x*xj.y - A.y*xj.x);
                    }
                }
                // write G_conj: i=(k*8+d) -> G[k][d][e]
                { int i = lane;      s->G[i>>3][i&7][e] = x0; }
                if (lane < 8) { int i = lane + 32; s->G[i>>3][i&7][e] = x1; }
            }
            __syncthreads();

            // ---- reverb: E[e][t] = Y[e][t] - sum_{p,d} G[p][d][e]*Y[d][t-3-p]
            // single-pass 19 frames/lane; padded Y -> NO load guards.
            // iter-1: accumulate |E|^2 into invp (ps). iter-2: store E to g_E.
            {
                int lane = tid & 31, e = tid >> 5;
                int t0 = lane * 19;
                float2* Eg = g_E + ((size_t)bf * CC + e) * TT;
                u64 acc[19];
#pragma unroll
                for (int i = 0; i < 19; i++) {
                    float2 y = s->Y[e][t0 + i + TOFF];   // pad reads give zeros
                    acc[i] = pk2(y.x, y.y);
                }
#pragma unroll
                for (int d = 0; d < CC; d++) {
                    u64 gxn[NTAPS], gys[NTAPS];
#pragma unroll
                    for (int p = 0; p < NTAPS; p++) {
                        float2 g = s->G[p][d][e];        // broadcast LDS
                        gxn[p] = pk2(-g.x, -g.x);
                        gys[p] = pk2(g.y, -g.y);
                    }
                    u64 w[NTAPS], ws[NTAPS];
#pragma unroll
                    for (int p = 0; p < NTAPS-1; p++) {
                        float2 y = s->Y[d][t0 - 4 - p + TOFF];  // pad-safe
                        w[p]  = pk2(y.x, y.y);
                        ws[p] = pk2(y.y, y.x);
                    }
                    w[NTAPS-1] = ws[NTAPS-1] = 0ull;
#pragma unroll
                    for (int i = 0; i < 19; i++) {
#pragma unroll
                        for (int p = NTAPS-1; p > 0; p--) { w[p]=w[p-1]; ws[p]=ws[p-1]; }
                        float2 y = s->Y[d][t0 + i - 3 + TOFF];  // pad-safe both ends
                        w[0]  = pk2(y.x, y.y);
                        ws[0] = pk2(y.y, y.x);
#pragma unroll
                        for (int p = 0; p < NTAPS; p++) {
                            acc[i] = fma2(gxn[p], w[p],  acc[i]);
                            acc[i] = fma2(gys[p], ws[p], acc[i]);
                        }
                    }
                }
                if (it == 0) {
#pragma unroll
                    for (int i = 0; i < 19; i++) {
                        int t = t0 + i;
                        if (t < TT) {
                            float2 v = upk2(acc[i]);
                            atomicAdd(&s->invp[t + IOFF], v.x*v.x + v.y*v.y);
                        }
                    }
                    __syncthreads();    // ps complete before iter-2 power
                } else {
#pragma unroll
                    for (int i = 0; i < 19; i++) {
                        int t = t0 + i;
                        if (t < TT) Eg[t] = upk2(acc[i]);
                    }
                }
            }
        } // iterations

        __syncthreads();   // all warps done reading s->Y before next job reload
    } // persistent job loop
}

// ---------------------------------------------------------------------------
extern "C" void kernel_launch(void* const* d_in, const int* in_sizes, int n_in,
                              void* d_out, int out_size) {
    const float* re    = (const float*)d_in[0];
    const float* im    = (const float*)d_in[1];
    const int*   ilens = (const int*)d_in[2];
    float* out = (float*)d_out;

    cudaFuncSetAttribute(k_wpe, cudaFuncAttributeMaxDynamicSharedMemorySize,
                         (int)sizeof(WpeSmem));

    dim3 blk(32, 8);
    k_transpose_in<<<dim3((FF+31)/32, (TT+31)/32, BB*CC), blk>>>(re, im);
    k_wpe<<<NCTAS, NTHREADS, sizeof(WpeSmem)>>>();
    k_transpose_out<<<dim3((TT+31)/32, (FF+31)/32, BB*CC), blk>>>(out, ilens);
}

// round 13
// speedup vs baseline: 1.0846x; 1.0846x over previous
#include <cuda_runtime.h>
#include <math.h>

// Problem constants (fixed by setup_inputs)
#define BB 8
#define TT 600
#define CC 8
#define FF 257
#define NTAPS 5
#define NDELAY 3
#define KC 40           // NTAPS*CC
#define EPSV 1e-10f
#define NTHREADS 256
#define NJOBS (BB*FF)   // 2056
// valid frame count Tq = T - DELAY - TAPS + 1 = 593; u in [4, 597)

// Padded Y row: 8 leading zeros + 600 data + 10 trailing zeros = 618 float2.
// Row stride 618*8 B: 16B-aligned rows (float4 loads OK); bank offsets between
// rows = 20 mod 32 -> all 8 channel rows on distinct banks.
#define TP 618
#define TOFF 8
#define IOFF 1          // invp values at [IOFF+t] so invp[IOFF+u+3] is 16B-aligned

typedef unsigned long long u64;

// Scratch: Y and enhanced in (B,F,C,T) complex layout
__device__ float2 g_Y[(size_t)BB*FF*CC*TT];
__device__ float2 g_E[(size_t)BB*FF*CC*TT];

struct WpeSmem {
    float2 Y[CC][TP];          // 39552 B  (zero-padded both ends)
    float  invp[604];          //  2416 B  (weights during R/P; ps after)
    float2 R[KC][KC+1];        // 13120 B  (padded row; dinv lives in diag .y)
    float2 P[NTAPS][CC][CC];   //  2560 B  [k][e][d]
    float2 X[CC][KC];          //  2560 B  RHS panel, forward-solved in LDL
    float2 G[NTAPS][CC][CC];   //  2560 B  [p][d][e]
};                             // ~62768 B -> 3 CTAs/SM

// ---------------- packed f32x2 helpers (sm_103a FFMA2 path) ----------------
__device__ __forceinline__ u64 pk2(float lo, float hi) {
    u64 r; asm("mov.b64 %0, {%1, %2};" : "=l"(r) : "f"(lo), "f"(hi)); return r;
}
__device__ __forceinline__ float2 upk2(u64 v) {
    float2 r; asm("mov.b64 {%0, %1}, %2;" : "=f"(r.x), "=f"(r.y) : "l"(v)); return r;
}
__device__ __forceinline__ u64 fma2(u64 a, u64 b, u64 c) {
    u64 d; asm("fma.rn.f32x2 %0, %1, %2, %3;" : "=l"(d) : "l"(a), "l"(b), "l"(c)); return d;
}
__device__ __forceinline__ u64 mul2(u64 a, u64 b) {
    u64 d; asm("mul.rn.f32x2 %0, %1, %2;" : "=l"(d) : "l"(a), "l"(b)); return d;
}
// broadcast one lane of a packed pair into both lanes
__device__ __forceinline__ u64 bcast_lo(u64 v) {
    u64 r; asm("{\n\t.reg .f32 a,b;\n\tmov.b64 {a,b}, %1;\n\tmov.b64 %0, {a,a};\n\t}"
               : "=l"(r) : "l"(v)); return r;
}
__device__ __forceinline__ u64 bcast_hi(u64 v) {
    u64 r; asm("{\n\t.reg .f32 a,b;\n\tmov.b64 {a,b}, %1;\n\tmov.b64 %0, {b,b};\n\t}"
               : "=l"(r) : "l"(v)); return r;
}
__device__ __forceinline__ float2 shfl2(float2 v, int src) {
    float2 r;
    r.x = __shfl_sync(0xffffffffu, v.x, src);
    r.y = __shfl_sync(0xffffffffu, v.y, src);
    return r;
}

// ---------------------------------------------------------------------------
// Transpose in: (B,T,C,F) real+imag planes -> g_Y (B,F,C,T) float2
// ---------------------------------------------------------------------------
__global__ void k_transpose_in(const float* __restrict__ re,
                               const float* __restrict__ im) {
    __shared__ float2 tile[32][33];
    int bc = blockIdx.z;
    int b = bc / CC, c = bc % CC;
    int f0 = blockIdx.x * 32, t0 = blockIdx.y * 32;
    int tx = threadIdx.x, ty = threadIdx.y;
#pragma unroll
    for (int j = 0; j < 4; j++) {
        int t = t0 + ty + j*8, f = f0 + tx;
        if (t < TT && f < FF) {
            size_t idx = ((size_t)(b*TT + t)*CC + c)*FF + f;
            tile[ty + j*8][tx] = make_float2(re[idx], im[idx]);
        }
    }
    __syncthreads();
#pragma unroll
    for (int j = 0; j < 4; j++) {
        int f = f0 + ty + j*8, t = t0 + tx;
        if (t < TT && f < FF) {
            g_Y[((size_t)(b*FF + f)*CC + c)*TT + t] = tile[tx][ty + j*8];
        }
    }
}

// ---------------------------------------------------------------------------
// Transpose out: g_E (B,F,C,T) -> out real/imag planes (B,T,C,F), masked
// ---------------------------------------------------------------------------
__global__ void k_transpose_out(float* __restrict__ out,
                                const int* __restrict__ ilens) {
    __shared__ float2 tile[32][33];
    int bc = blockIdx.z;
    int b = bc / CC, c = bc % CC;
    int t0 = blockIdx.x * 32, f0 = blockIdx.y * 32;
    int tx = threadIdx.x, ty = threadIdx.y;
    int ilen = ilens[b];
    const size_t N = (size_t)BB*TT*CC*FF;
#pragma unroll
    for (int j = 0; j < 4; j++) {
        int f = f0 + ty + j*8, t = t0 + tx;
        if (t < TT && f < FF) {
            tile[ty + j*8][tx] = g_E[((size_t)(b*FF + f)*CC + c)*TT + t];
        }
    }
    __syncthreads();
#pragma unroll
    for (int j = 0; j < 4; j++) {
        int t = t0 + ty + j*8, f = f0 + tx;
        if (t < TT && f < FF) {
            float2 v = tile[tx][ty + j*8];
            if (t >= ilen) v = make_float2(0.f, 0.f);
            size_t idx = ((size_t)(b*TT + t)*CC + c)*FF + f;
            out[idx]     = v.x;
            out[N + idx] = v.y;
        }
    }
}

// ---------------------------------------------------------------------------
// Fused WPE: one CTA per (b,f). 2 iterations entirely in shared memory.
// ---------------------------------------------------------------------------
__global__ __launch_bounds__(NTHREADS, 3) void k_wpe() {
    extern __shared__ char smem_raw[];
    WpeSmem* s = (WpeSmem*)smem_raw;
    int bf = blockIdx.x;
    int tid = threadIdx.x;

    // Load Y rows into padded smem; zero the pads.
    const float2* Yg = g_Y + (size_t)bf * CC * TT;
#pragma unroll
    for (int c = 0; c < CC; c++)
        for (int t = tid; t < TT; t += NTHREADS)
            s->Y[c][t + TOFF] = Yg[c*TT + t];
    if (tid < CC * 18) {                 // 8 front + 10 back pads per row
        int c = tid / 18, p = tid % 18;
        int idx = (p < TOFF) ? p : (TT + p);   // 0..7 and 608..617
        s->Y[c][idx] = make_float2(0.f, 0.f);
    }
    __syncthreads();

    for (int it = 0; it < 2; it++) {
        // ---- power -> invp ----
        if (it == 0) {
            for (int t = tid; t < TT; t += NTHREADS) {
                float sum = 0.f;
#pragma unroll
                for (int c = 0; c < CC; c++) {
                    float2 y = s->Y[c][t + TOFF];
                    sum += y.x*y.x + y.y*y.y;
                }
                s->invp[t + IOFF] = 1.0f / fmaxf(sum * (1.0f / CC), EPSV);
            }
        } else {
            // invp currently holds ps (|E1|^2 sums); convert in place
            for (int t = tid; t < TT; t += NTHREADS)
                s->invp[t + IOFF] =
                    1.0f / fmaxf(s->invp[t + IOFF] * (1.0f / CC), EPSV);
        }
        __syncthreads();

        // ---- fused R + P accumulation, single pass over full u range ----
        // Split-accumulator scheme: for conj(c)*z with weight w,
        //   accA += (w*cx,w*cx) (x) (zx,zy); accB += (w*cy,w*cy) (x) (zx,zy)
        //   re = A.lo + B.hi ;  im = A.hi - B.lo
        // Broadcast trick: s2 = w*(cx,cy) via one mul2 on the loaded pair;
        // aw = bcast_lo(s2), bw = bcast_hi(s2)  -> 1 mul2 instead of 2.
        // R jobs: threads 0..179 = (pair d<=e [36], k [5]).
        // P jobs: threads 192..255 = ordered pair (d,e) [64].
        if (tid < 180) {
            int pair = tid / 5, k = tid % 5;
            int e = 0;
            while ((e+1)*(e+2)/2 <= pair) e++;
            int d = pair - e*(e+1)/2;            // d <= e
            u64 accA[NTAPS], accB[NTAPS];
#pragma unroll
            for (int l = 0; l < NTAPS; l++) { accA[l] = 0ull; accB[l] = 0ull; }
            u64 wep[NTAPS];                      // wep[l] = Ye[u-1-l] pack (x,y)
#pragma unroll
            for (int l = 0; l < NTAPS-1; l++) {
                float2 y = s->Y[e][3 - l + TOFF];
                wep[l] = pk2(y.x, y.y);
            }
            wep[NTAPS-1] = 0ull;

            for (int u = 4; u < 596; u += 4) {
                float4 w4  = *reinterpret_cast<const float4*>(&s->invp[IOFF + u + 3]);
                float4 yeA = *reinterpret_cast<const float4*>(&s->Y[e][u + TOFF]);
                float4 yeB = *reinterpret_cast<const float4*>(&s->Y[e][u + 2 + TOFF]);
                float wj[4]  = {w4.x, w4.y, w4.z, w4.w};
                float yex[4] = {yeA.x, yeA.z, yeB.x, yeB.z};
                float yey[4] = {yeA.y, yeA.w, yeB.y, yeB.w};
#pragma unroll
                for (int j = 0; j < 4; j++) {
#pragma unroll
                    for (int l = NTAPS-1; l > 0; l--) wep[l] = wep[l-1];
                    wep[0] = pk2(yex[j], yey[j]);
                    float2 yd = s->Y[d][u + j - k + TOFF];
                    u64 s2 = mul2(pk2(wj[j], wj[j]), pk2(yd.x, yd.y));
                    u64 aw = bcast_lo(s2);
                    u64 bw = bcast_hi(s2);
#pragma unroll
                    for (int l = 0; l < NTAPS; l++) {
                        accA[l] = fma2(aw, wep[l], accA[l]);
                        accB[l] = fma2(bw, wep[l], accB[l]);
                    }
                }
            }
            {   // remainder u = 596
                const int u = 596;
#pragma unroll
                for (int l = NTAPS-1; l > 0; l--) wep[l] = wep[l-1];
                float2 ye = s->Y[e][u + TOFF];
                wep[0] = pk2(ye.x, ye.y);
                float2 yd = s->Y[d][u - k + TOFF];
                float w = s->invp[IOFF + u + 3];
                u64 s2 = mul2(pk2(w, w), pk2(yd.x, yd.y));
                u64 aw = bcast_lo(s2);
                u64 bw = bcast_hi(s2);
#pragma unroll
                for (int l = 0; l < NTAPS; l++) {
                    accA[l] = fma2(aw, wep[l], accA[l]);
                    accB[l] = fma2(bw, wep[l], accB[l]);
                }
            }
#pragma unroll
            for (int l = 0; l < NTAPS; l++) {
                float2 A = upk2(accA[l]), B = upk2(accB[l]);
                float2 v = make_float2(A.x + B.y, A.y - B.x);
                s->R[k*CC + d][l*CC + e] = v;
                if (d < e)
                    s->R[l*CC + e][k*CC + d] = make_float2(v.x, -v.y);
            }
        } else if (tid >= 192) {
            int pair = tid - 192;
            int d = pair & 7, e = pair >> 3;
            u64 accA[NTAPS], accB[NTAPS];
#pragma unroll
            for (int k = 0; k < NTAPS; k++) { accA[k] = 0ull; accB[k] = 0ull; }
            u64 dxx[NTAPS], dyy[NTAPS];          // window of Yd[u-k] broadcast packs
#pragma unroll
            for (int k = 0; k < NTAPS-1; k++) {
                float2 yd = s->Y[d][3 - k + TOFF];
                dxx[k] = pk2(yd.x, yd.x);
                dyy[k] = pk2(yd.y, yd.y);
            }
            dxx[NTAPS-1] = dyy[NTAPS-1] = 0ull;

            for (int u = 4; u < 596; u += 4) {
                float4 w4  = *reinterpret_cast<const float4*>(&s->invp[IOFF + u + 3]);
                float4 ydA = *reinterpret_cast<const float4*>(&s->Y[d][u + TOFF]);
                float4 ydB = *reinterpret_cast<const float4*>(&s->Y[d][u + 2 + TOFF]);
                float wj[4]  = {w4.x, w4.y, w4.z, w4.w};
                float ydx[4] = {ydA.x, ydA.z, ydB.x, ydB.z};
                float ydy[4] = {ydA.y, ydA.w, ydB.y, ydB.w};
#pragma unroll
                for (int j = 0; j < 4; j++) {
#pragma unroll
                    for (int k = NTAPS-1; k > 0; k--) { dxx[k]=dxx[k-1]; dyy[k]=dyy[k-1]; }
                    dxx[0] = pk2(ydx[j], ydx[j]);
                    dyy[0] = pk2(ydy[j], ydy[j]);
                    float2 ye = s->Y[e][u + j + 3 + TOFF];
                    u64 sv = mul2(pk2(wj[j], wj[j]), pk2(ye.x, ye.y));
#pragma unroll
                    for (int k = 0; k < NTAPS; k++) {
                        accA[k] = fma2(dxx[k], sv, accA[k]);
                        accB[k] = fma2(dyy[k], sv, accB[k]);
                    }
                }
            }
            {   // remainder u = 596
                const int u = 596;
#pragma unroll
                for (int k = NTAPS-1; k > 0; k--) { dxx[k]=dxx[k-1]; dyy[k]=dyy[k-1]; }
                float2 yd = s->Y[d][u + TOFF];
                dxx[0] = pk2(yd.x, yd.x);
                dyy[0] = pk2(yd.y, yd.y);
                float2 ye = s->Y[e][u + 3 + TOFF];
                float w = s->invp[IOFF + u + 3];
                u64 sv = mul2(pk2(w, w), pk2(ye.x, ye.y));
#pragma unroll
                for (int k = 0; k < NTAPS; k++) {
                    accA[k] = fma2(dxx[k], sv, accA[k]);
                    accB[k] = fma2(dyy[k], sv, accB[k]);
                }
            }
#pragma unroll
            for (int k = 0; k < NTAPS; k++) {
                float2 A = upk2(accA[k]), B = upk2(accB[k]);
                s->P[k][e][d] = make_float2(A.x + B.y, A.y - B.x);
            }
        }
        __syncthreads();

        // ---- weights dead: repurpose invp as ps accumulator (zero it);
        //      regularize R diag; stage RHS panel X[e][i] = P (i=(k*8+d)).
        //      All covered by LDL's first barrier. ----
        for (int t = tid; t < TT; t += NTHREADS) s->invp[t + IOFF] = 0.f;
        if (tid < KC) s->R[tid][tid].x += EPSV;
        {
            int lane = tid & 31, e = tid >> 5;
            for (int i = lane; i < KC; i += 32)
                s->X[e][i] = s->P[i>>3][e][i&7];
        }

        // ---- in-place LDL^H of R with fused forward solve of the 8 RHS:
        //      one barrier per column; dinv -> R[j][j].y.
        //      X columns get the same elimination: X[e][i] -= Aw * X[e][j]
        //      (plain complex multiply; after the loop X holds y = L^{-1} b).
        for (int j = 0; j < KC; j++) {
            __syncthreads();                 // column j fully updated
            float djj = s->R[j][j].x;        // broadcast read
            float dinv = 1.0f / fmaxf(djj, 1e-30f);
            if (tid == 0) s->R[j][j].y = dinv;
            int w = tid >> 5;                // 0..7 (l-stride / rhs column)
            float2 Xj = s->X[w][j];
            for (int i = j + 1 + (tid & 31); i < KC; i += 32) {
                float2 Aij = s->R[i][j];
                float2 Aw = make_float2(Aij.x * dinv, Aij.y * dinv);
                for (int l = j + 1 + w; l <= i; l += 8) {
                    float2 Alj = s->R[l][j];
                    s->R[i][l].x -= Aw.x*Alj.x + Aw.y*Alj.y;
                    s->R[i][l].y -= Aw.y*Alj.x - Aw.x*Alj.y;
                }
                // fused forward solve: rhs column w, row i
                s->X[w][i].x -= Aw.x*Xj.x - Aw.y*Xj.y;
                s->X[w][i].y -= Aw.x*Xj.y + Aw.y*Xj.x;
            }
        }
        __syncthreads();

        // ---- backward solve in registers: warp e solves channel e ----
        {
            int lane = tid & 31, e = tid >> 5;
            float2 x0, x1;
            x0 = s->X[e][lane];
            x1 = (lane < 8) ? s->X[e][lane + 32] : make_float2(0.f, 0.f);
            float dinv0 = s->R[lane][lane].y;
            float dinv1 = (lane < 8) ? s->R[lane+32][lane+32].y : 0.f;

            // z = D^{-1} y
            x0.x *= dinv0; x0.y *= dinv0;
            x1.x *= dinv1; x1.y *= dinv1;
            // backward: L^H x = z ;  x_i -= dinv_i * conj(A[j][i]) * x_j, i<j
            for (int j = KC - 1; j >= 1; j--) {
                int src = j & 31;
                float2 xj = (j < 32) ? shfl2(x0, src) : shfl2(x1, src);
                if (lane < j) {
                    float2 A = s->R[j][lane];
                    x0.x -= dinv0 * (A.x*xj.x + A.y*xj.y);
                    x0.y -= dinv0 * (A.x*xj.y - A.y*xj.x);
                }
                if (lane < 8 && lane + 32 < j) {
                    float2 A = s->R[j][lane+32];
                    x1.x -= dinv1 * (A.x*xj.x + A.y*xj.y);
                    x1.y -= dinv1 * (A.x*xj.y - A.y*xj.x);
                }
            }
            // write G_conj: i=(k*8+d) -> G[k][d][e]
            { int i = lane;      s->G[i>>3][i&7][e] = x0; }
            if (lane < 8) { int i = lane + 32; s->G[i>>3][i&7][e] = x1; }
        }
        __syncthreads();

        // ---- reverb: E[e][t] = Y[e][t] - sum_{p,d} G[p][d][e]*Y[d][t-3-p]
        // single-pass 19 frames/lane; padded Y -> NO load guards.
        // iter-1: accumulate |E|^2 into invp (ps). iter-2: store E to g_E.
        {
            int lane = tid & 31, e = tid >> 5;
            int t0 = lane * 19;
            float2* Eg = g_E + ((size_t)bf * CC + e) * TT;
            u64 acc[19];
#pragma unroll
            for (int i = 0; i < 19; i++) {
                float2 y = s->Y[e][t0 + i + TOFF];   // pad reads give zeros
                acc[i] = pk2(y.x, y.y);
            }
#pragma unroll
            for (int d = 0; d < CC; d++) {
                u64 gxn[NTAPS], gys[NTAPS];
#pragma unroll
                for (int p = 0; p < NTAPS; p++) {
                    float2 g = s->G[p][d][e];        // broadcast LDS
                    gxn[p] = pk2(-g.x, -g.x);
                    gys[p] = pk2(g.y, -g.y);
                }
                u64 w[NTAPS], ws[NTAPS];
#pragma unroll
                for (int p = 0; p < NTAPS-1; p++) {
                    float2 y = s->Y[d][t0 - 4 - p + TOFF];  // pad-safe
                    w[p]  = pk2(y.x, y.y);
                    ws[p] = pk2(y.y, y.x);
                }
                w[NTAPS-1] = ws[NTAPS-1] = 0ull;
#pragma unroll
                for (int i = 0; i < 19; i++) {
#pragma unroll
                    for (int p = NTAPS-1; p > 0; p--) { w[p]=w[p-1]; ws[p]=ws[p-1]; }
                    float2 y = s->Y[d][t0 + i - 3 + TOFF];  // pad-safe both ends
                    w[0]  = pk2(y.x, y.y);
                    ws[0] = pk2(y.y, y.x);
#pragma unroll
                    for (int p = 0; p < NTAPS; p++) {
                        acc[i] = fma2(gxn[p], w[p],  acc[i]);
                        acc[i] = fma2(gys[p], ws[p], acc[i]);
                    }
                }
            }
            if (it == 0) {
#pragma unroll
                for (int i = 0; i < 19; i++) {
                    int t = t0 + i;
                    if (t < TT) {
                        float2 v = upk2(acc[i]);
                        atomicAdd(&s->invp[t + IOFF], v.x*v.x + v.y*v.y);
                    }
                }
                __syncthreads();    // ps complete before iter-2 power
            } else {
#pragma unroll
                for (int i = 0; i < 19; i++) {
                    int t = t0 + i;
                    if (t < TT) Eg[t] = upk2(acc[i]);
                }
            }
        }
    } // iterations
}

// ---------------------------------------------------------------------------
extern "C" void kernel_launch(void* const* d_in, const int* in_sizes, int n_in,
                              void* d_out, int out_size) {
    const float* re    = (const float*)d_in[0];
    const float* im    = (const float*)d_in[1];
    const int*   ilens = (const int*)d_in[2];
    float* out = (float*)d_out;

    cudaFuncSetAttribute(k_wpe, cudaFuncAttributeMaxDynamicSharedMemorySize,
                         (int)sizeof(WpeSmem));

    dim3 blk(32, 8);
    k_transpose_in<<<dim3((FF+31)/32, (TT+31)/32, BB*CC), blk>>>(re, im);
    k_wpe<<<NJOBS, NTHREADS, sizeof(WpeSmem)>>>();
    k_transpose_out<<<dim3((TT+31)/32, (FF+31)/32, BB*CC), blk>>>(out, ilens);
}

// round 14
// speedup vs baseline: 1.0849x; 1.0003x over previous
#include <cuda_runtime.h>
#include <math.h>

// Problem constants (fixed by setup_inputs)
#define BB 8
#define TT 600
#define CC 8
#define FF 257
#define NTAPS 5
#define NDELAY 3
#define KC 40           // NTAPS*CC
#define EPSV 1e-10f
#define NTHREADS 256
#define NJOBS (BB*FF)   // 2056
// valid frame count Tq = T - DELAY - TAPS + 1 = 593; u in [4, 597)

// Padded Y row: 8 leading zeros + 600 data + 10 trailing zeros = 618 float2.
// Row stride 618*8 B: 16B-aligned rows; bank offsets between rows = 20 mod 32
// -> all 8 channel rows on distinct banks.
#define TP 618
#define TOFF 8
#define IOFF 1          // invp values at [IOFF+t] so invp[IOFF+u0+3] is 16B-aligned

typedef unsigned long long u64;

// Scratch: Y and enhanced in (B,F,C,T) complex layout
__device__ float2 g_Y[(size_t)BB*FF*CC*TT];
__device__ float2 g_E[(size_t)BB*FF*CC*TT];

struct WpeSmem {
    float2 Y[CC][TP];          // 39552 B  (zero-padded both ends)
    float  invp[604];          //  2416 B  (weights during R/P; ps after)
    float2 R[KC][KC+1];        // 13120 B  (padded row; dinv lives in diag .y)
    float2 P[NTAPS][CC][CC];   //  2560 B  [k][e][d]
    float2 X[CC][KC];          //  2560 B  RHS panel, forward-solved in LDL
    float2 G[NTAPS][CC][CC];   //  2560 B  [p][d][e]
};                             // ~62768 B -> 3 CTAs/SM

// ---------------- packed f32x2 helpers (sm_103a FFMA2 path) ----------------
__device__ __forceinline__ u64 pk2(float lo, float hi) {
    u64 r; asm("mov.b64 %0, {%1, %2};" : "=l"(r) : "f"(lo), "f"(hi)); return r;
}
__device__ __forceinline__ float2 upk2(u64 v) {
    float2 r; asm("mov.b64 {%0, %1}, %2;" : "=f"(r.x), "=f"(r.y) : "l"(v)); return r;
}
__device__ __forceinline__ u64 fma2(u64 a, u64 b, u64 c) {
    u64 d; asm("fma.rn.f32x2 %0, %1, %2, %3;" : "=l"(d) : "l"(a), "l"(b), "l"(c)); return d;
}
__device__ __forceinline__ u64 mul2(u64 a, u64 b) {
    u64 d; asm("mul.rn.f32x2 %0, %1, %2;" : "=l"(d) : "l"(a), "l"(b)); return d;
}
// broadcast one lane of a packed pair into both lanes
__device__ __forceinline__ u64 bcast_lo(u64 v) {
    u64 r; asm("{\n\t.reg .f32 a,b;\n\tmov.b64 {a,b}, %1;\n\tmov.b64 %0, {a,a};\n\t}"
               : "=l"(r) : "l"(v)); return r;
}
__device__ __forceinline__ u64 bcast_hi(u64 v) {
    u64 r; asm("{\n\t.reg .f32 a,b;\n\tmov.b64 {a,b}, %1;\n\tmov.b64 %0, {b,b};\n\t}"
               : "=l"(r) : "l"(v)); return r;
}
__device__ __forceinline__ float2 shfl2(float2 v, int src) {
    float2 r;
    r.x = __shfl_sync(0xffffffffu, v.x, src);
    r.y = __shfl_sync(0xffffffffu, v.y, src);
    return r;
}
// load a float2 from smem directly as a u64 pack (operand-ready for fma2)
__device__ __forceinline__ u64 ldpk(const float2* p) {
    return *reinterpret_cast<const u64*>(p);
}

// ---------------------------------------------------------------------------
// Transpose in: (B,T,C,F) real+imag planes -> g_Y (B,F,C,T) float2
// ---------------------------------------------------------------------------
__global__ void k_transpose_in(const float* __restrict__ re,
                               const float* __restrict__ im) {
    __shared__ float2 tile[32][33];
    int bc = blockIdx.z;
    int b = bc / CC, c = bc % CC;
    int f0 = blockIdx.x * 32, t0 = blockIdx.y * 32;
    int tx = threadIdx.x, ty = threadIdx.y;
#pragma unroll
    for (int j = 0; j < 4; j++) {
        int t = t0 + ty + j*8, f = f0 + tx;
        if (t < TT && f < FF) {
            size_t idx = ((size_t)(b*TT + t)*CC + c)*FF + f;
            tile[ty + j*8][tx] = make_float2(re[idx], im[idx]);
        }
    }
    __syncthreads();
#pragma unroll
    for (int j = 0; j < 4; j++) {
        int f = f0 + ty + j*8, t = t0 + tx;
        if (t < TT && f < FF) {
            g_Y[((size_t)(b*FF + f)*CC + c)*TT + t] = tile[tx][ty + j*8];
        }
    }
}

// ---------------------------------------------------------------------------
// Transpose out: g_E (B,F,C,T) -> out real/imag planes (B,T,C,F), masked
// ---------------------------------------------------------------------------
__global__ void k_transpose_out(float* __restrict__ out,
                                const int* __restrict__ ilens) {
    __shared__ float2 tile[32][33];
    int bc = blockIdx.z;
    int b = bc / CC, c = bc % CC;
    int t0 = blockIdx.x * 32, f0 = blockIdx.y * 32;
    int tx = threadIdx.x, ty = threadIdx.y;
    int ilen = ilens[b];
    const size_t N = (size_t)BB*TT*CC*FF;
#pragma unroll
    for (int j = 0; j < 4; j++) {
        int f = f0 + ty + j*8, t = t0 + tx;
        if (t < TT && f < FF) {
            tile[ty + j*8][tx] = g_E[((size_t)(b*FF + f)*CC + c)*TT + t];
        }
    }
    __syncthreads();
#pragma unroll
    for (int j = 0; j < 4; j++) {
        int t = t0 + ty + j*8, f = f0 + tx;
        if (t < TT && f < FF) {
            float2 v = tile[tx][ty + j*8];
            if (t >= ilen) v = make_float2(0.f, 0.f);
            size_t idx = ((size_t)(b*TT + t)*CC + c)*FF + f;
            out[idx]     = v.x;
            out[N + idx] = v.y;
        }
    }
}

// ---------------------------------------------------------------------------
// Fused WPE: one CTA per (b,f). 2 iterations entirely in shared memory.
// ---------------------------------------------------------------------------
__global__ __launch_bounds__(NTHREADS, 3) void k_wpe() {
    extern __shared__ char smem_raw[];
    WpeSmem* s = (WpeSmem*)smem_raw;
    int bf = blockIdx.x;
    int tid = threadIdx.x;

    // Load Y rows into padded smem; zero the pads.
    const float2* Yg = g_Y + (size_t)bf * CC * TT;
#pragma unroll
    for (int c = 0; c < CC; c++)
        for (int t = tid; t < TT; t += NTHREADS)
            s->Y[c][t + TOFF] = Yg[c*TT + t];
    if (tid < CC * 18) {                 // 8 front + 10 back pads per row
        int c = tid / 18, p = tid % 18;
        int idx = (p < TOFF) ? p : (TT + p);   // 0..7 and 608..617
        s->Y[c][idx] = make_float2(0.f, 0.f);
    }
    __syncthreads();

    for (int it = 0; it < 2; it++) {
        // ---- power -> invp ----
        if (it == 0) {
            for (int t = tid; t < TT; t += NTHREADS) {
                float sum = 0.f;
#pragma unroll
                for (int c = 0; c < CC; c++) {
                    float2 y = s->Y[c][t + TOFF];
                    sum += y.x*y.x + y.y*y.y;
                }
                s->invp[t + IOFF] = 1.0f / fmaxf(sum * (1.0f / CC), EPSV);
            }
        } else {
            // invp currently holds ps (|E1|^2 sums); convert in place
            for (int t = tid; t < TT; t += NTHREADS)
                s->invp[t + IOFF] =
                    1.0f / fmaxf(s->invp[t + IOFF] * (1.0f / CC), EPSV);
        }
        __syncthreads();

        // ---- fused R + P accumulation, single pass over full u range ----
        // Static-select windows: 8-u chunks keep 12 u64 packs of the windowed
        // stream (direct LDS.64 -> fma2 operand, no shift MOVs, no pack MOVs).
        // R jobs: threads 0..179 = (pair d<=e [36], k [5]).
        //   accA[l] += (w*ydx,w*ydx) (x) Ye[u-l]pk ; accB[l] += (w*ydy,..)
        //   re = A.lo + B.hi ; im = A.hi - B.lo
        // P jobs: threads 192..255 = ordered pair (d,e) [64].
        //   window = Yd pair packs; broadcast = sv = w*Ye[u+3]
        //   accA[k] += Yd[u-k]pk (x) (svx,svx) ; accB[k] += Yd[u-k]pk (x) (svy,svy)
        //   re = A.lo + B.hi ; im = B.lo - A.hi
        if (tid < 180) {
            int pair = tid / 5, k = tid % 5;
            int e = 0;
            while ((e+1)*(e+2)/2 <= pair) e++;
            int d = pair - e*(e+1)/2;            // d <= e
            u64 accA[NTAPS], accB[NTAPS];
#pragma unroll
            for (int l = 0; l < NTAPS; l++) { accA[l] = 0ull; accB[l] = 0ull; }
            u64 pe[12];                          // pe[c] = Ye[u0-4+c] pack
#pragma unroll
            for (int c = 0; c < 4; c++) pe[c] = ldpk(&s->Y[e][c + TOFF]);

            for (int u0 = 4; u0 < 596; u0 += 8) {
                float4 w4a = *reinterpret_cast<const float4*>(&s->invp[IOFF + u0 + 3]);
                float4 w4b = *reinterpret_cast<const float4*>(&s->invp[IOFF + u0 + 7]);
#pragma unroll
                for (int c = 0; c < 8; c++)
                    pe[4 + c] = ldpk(&s->Y[e][u0 + c + TOFF]);
                float wj[8] = {w4a.x, w4a.y, w4a.z, w4a.w,
                               w4b.x, w4b.y, w4b.z, w4b.w};
#pragma unroll
                for (int j = 0; j < 8; j++) {
                    float2 yd = s->Y[d][u0 + j - k + TOFF];
                    u64 s2 = mul2(pk2(wj[j], wj[j]), pk2(yd.x, yd.y));
                    u64 aw = bcast_lo(s2);
                    u64 bw = bcast_hi(s2);
#pragma unroll
                    for (int l = 0; l < NTAPS; l++) {
                        accA[l] = fma2(aw, pe[j + 4 - l], accA[l]);
                        accB[l] = fma2(bw, pe[j + 4 - l], accB[l]);
                    }
                }
#pragma unroll
                for (int c = 0; c < 4; c++) pe[c] = pe[8 + c];
            }
            {   // remainder u = 596 (pe[0..3] = Ye[592..595])
                pe[4] = ldpk(&s->Y[e][596 + TOFF]);
                float2 yd = s->Y[d][596 - k + TOFF];
                float w = s->invp[IOFF + 599];
                u64 s2 = mul2(pk2(w, w), pk2(yd.x, yd.y));
                u64 aw = bcast_lo(s2);
                u64 bw = bcast_hi(s2);
#pragma unroll
                for (int l = 0; l < NTAPS; l++) {
                    accA[l] = fma2(aw, pe[4 - l], accA[l]);
                    accB[l] = fma2(bw, pe[4 - l], accB[l]);
                }
            }
#pragma unroll
            for (int l = 0; l < NTAPS; l++) {
                float2 A = upk2(accA[l]), B = upk2(accB[l]);
                float2 v = make_float2(A.x + B.y, A.y - B.x);
                s->R[k*CC + d][l*CC + e] = v;
                if (d < e)
                    s->R[l*CC + e][k*CC + d] = make_float2(v.x, -v.y);
            }
        } else if (tid >= 192) {
            int pair = tid - 192;
            int d = pair & 7, e = pair >> 3;
            u64 accA[NTAPS], accB[NTAPS];
#pragma unroll
            for (int k = 0; k < NTAPS; k++) { accA[k] = 0ull; accB[k] = 0ull; }
            u64 pdw[12];                         // pdw[c] = Yd[u0-4+c] pack
#pragma unroll
            for (int c = 0; c < 4; c++) pdw[c] = ldpk(&s->Y[d][c + TOFF]);

            for (int u0 = 4; u0 < 596; u0 += 8) {
                float4 w4a = *reinterpret_cast<const float4*>(&s->invp[IOFF + u0 + 3]);
                float4 w4b = *reinterpret_cast<const float4*>(&s->invp[IOFF + u0 + 7]);
#pragma unroll
                for (int c = 0; c < 8; c++)
                    pdw[4 + c] = ldpk(&s->Y[d][u0 + c + TOFF]);
                float wj[8] = {w4a.x, w4a.y, w4a.z, w4a.w,
                               w4b.x, w4b.y, w4b.z, w4b.w};
#pragma unroll
                for (int j = 0; j < 8; j++) {
                    float2 ye = s->Y[e][u0 + j + 3 + TOFF];
                    u64 sv = mul2(pk2(wj[j], wj[j]), pk2(ye.x, ye.y));
                    u64 svl = bcast_lo(sv);
                    u64 svh = bcast_hi(sv);
#pragma unroll
                    for (int k = 0; k < NTAPS; k++) {
                        accA[k] = fma2(pdw[j + 4 - k], svl, accA[k]);
                        accB[k] = fma2(pdw[j + 4 - k], svh, accB[k]);
                    }
                }
#pragma unroll
                for (int c = 0; c < 4; c++) pdw[c] = pdw[8 + c];
            }
            {   // remainder u = 596 (pdw[0..3] = Yd[592..595])
                pdw[4] = ldpk(&s->Y[d][596 + TOFF]);
                float2 ye = s->Y[e][599 + TOFF];
                float w = s->invp[IOFF + 599];
                u64 sv = mul2(pk2(w, w), pk2(ye.x, ye.y));
                u64 svl = bcast_lo(sv);
                u64 svh = bcast_hi(sv);
#pragma unroll
                for (int k = 0; k < NTAPS; k++) {
                    accA[k] = fma2(pdw[4 - k], svl, accA[k]);
                    accB[k] = fma2(pdw[4 - k], svh, accB[k]);
                }
            }
#pragma unroll
            for (int k = 0; k < NTAPS; k++) {
                float2 A = upk2(accA[k]), B = upk2(accB[k]);
                // re = ydx*svx + ydy*svy ; im = ydx*svy - ydy*svx
                s->P[k][e][d] = make_float2(A.x + B.y, B.x - A.y);
            }
        }
        __syncthreads();

        // ---- weights dead: repurpose invp as ps accumulator (zero it);
        //      regularize R diag; stage RHS panel X[e][i] = P (i=(k*8+d)).
        //      All covered by LDL's first barrier. ----
        for (int t = tid; t < TT; t += NTHREADS) s->invp[t + IOFF] = 0.f;
        if (tid < KC) s->R[tid][tid].x += EPSV;
        {
            int lane = tid & 31, e = tid >> 5;
            for (int i = lane; i < KC; i += 32)
                s->X[e][i] = s->P[i>>3][e][i&7];
        }

        // ---- in-place LDL^H of R with fused forward solve of the 8 RHS:
        //      one barrier per column; dinv -> R[j][j].y. ----
        for (int j = 0; j < KC; j++) {
            __syncthreads();                 // column j fully updated
            float djj = s->R[j][j].x;        // broadcast read
            float dinv = 1.0f / fmaxf(djj, 1e-30f);
            if (tid == 0) s->R[j][j].y = dinv;
            int w = tid >> 5;                // 0..7 (l-stride / rhs column)
            float2 Xj = s->X[w][j];
            for (int i = j + 1 + (tid & 31); i < KC; i += 32) {
                float2 Aij = s->R[i][j];
                float2 Aw = make_float2(Aij.x * dinv, Aij.y * dinv);
                for (int l = j + 1 + w; l <= i; l += 8) {
                    float2 Alj = s->R[l][j];
                    s->R[i][l].x -= Aw.x*Alj.x + Aw.y*Alj.y;
                    s->R[i][l].y -= Aw.y*Alj.x - Aw.x*Alj.y;
                }
                // fused forward solve: rhs column w, row i
                s->X[w][i].x -= Aw.x*Xj.x - Aw.y*Xj.y;
                s->X[w][i].y -= Aw.x*Xj.y + Aw.y*Xj.x;
            }
        }
        __syncthreads();

        // ---- backward solve in registers: warp e solves channel e ----
        {
            int lane = tid & 31, e = tid >> 5;
            float2 x0, x1;
            x0 = s->X[e][lane];
            x1 = (lane < 8) ? s->X[e][lane + 32] : make_float2(0.f, 0.f);
            float dinv0 = s->R[lane][lane].y;
            float dinv1 = (lane < 8) ? s->R[lane+32][lane+32].y : 0.f;

            // z = D^{-1} y
            x0.x *= dinv0; x0.y *= dinv0;
            x1.x *= dinv1; x1.y *= dinv1;
            // backward: L^H x = z ;  x_i -= dinv_i * conj(A[j][i]) * x_j, i<j
            for (int j = KC - 1; j >= 1; j--) {
                int src = j & 31;
                float2 xj = (j < 32) ? shfl2(x0, src) : shfl2(x1, src);
                if (lane < j) {
                    float2 A = s->R[j][lane];
                    x0.x -= dinv0 * (A.x*xj.x + A.y*xj.y);
                    x0.y -= dinv0 * (A.x*xj.y - A.y*xj.x);
                }
                if (lane < 8 && lane + 32 < j) {
                    float2 A = s->R[j][lane+32];
                    x1.x -= dinv1 * (A.x*xj.x + A.y*xj.y);
                    x1.y -= dinv1 * (A.x*xj.y - A.y*xj.x);
                }
            }
            // write G_conj: i=(k*8+d) -> G[k][d][e]
            { int i = lane;      s->G[i>>3][i&7][e] = x0; }
            if (lane < 8) { int i = lane + 32; s->G[i>>3][i&7][e] = x1; }
        }
        __syncthreads();

        // ---- reverb: E[e][t] = Y[e][t] - sum_{p,d} G[p][d][e]*Y[d][t-3-p]
        // single-pass 19 frames/lane; padded Y -> NO load guards.
        // iter-1: accumulate |E|^2 into invp (ps). iter-2: store E to g_E.
        {
            int lane = tid & 31, e = tid >> 5;
            int t0 = lane * 19;
            float2* Eg = g_E + ((size_t)bf * CC + e) * TT;
            u64 acc[19];
#pragma unroll
            for (int i = 0; i < 19; i++)
                acc[i] = ldpk(&s->Y[e][t0 + i + TOFF]);   // pad reads give zeros
#pragma unroll
            for (int d = 0; d < CC; d++) {
                u64 gxn[NTAPS], gys[NTAPS];
#pragma unroll
                for (int p = 0; p < NTAPS; p++) {
                    float2 g = s->G[p][d][e];        // broadcast LDS
                    gxn[p] = pk2(-g.x, -g.x);
                    gys[p] = pk2(g.y, -g.y);
                }
                u64 w[NTAPS], ws[NTAPS];
#pragma unroll
                for (int p = 0; p < NTAPS-1; p++) {
                    float2 y = s->Y[d][t0 - 4 - p + TOFF];  // pad-safe
                    w[p]  = pk2(y.x, y.y);
                    ws[p] = pk2(y.y, y.x);
                }
                w[NTAPS-1] = ws[NTAPS-1] = 0ull;
#pragma unroll
                for (int i = 0; i < 19; i++) {
#pragma unroll
                    for (int p = NTAPS-1; p > 0; p--) { w[p]=w[p-1]; ws[p]=ws[p-1]; }
                    float2 y = s->Y[d][t0 + i - 3 + TOFF];  // pad-safe both ends
                    w[0]  = pk2(y.x, y.y);
                    ws[0] = pk2(y.y, y.x);
#pragma unroll
                    for (int p = 0; p < NTAPS; p++) {
                        acc[i] = fma2(gxn[p], w[p],  acc[i]);
                        acc[i] = fma2(gys[p], ws[p], acc[i]);
                    }
                }
            }
            if (it == 0) {
#pragma unroll
                for (int i = 0; i < 19; i++) {
                    int t = t0 + i;
                    if (t < TT) {
                        float2 v = upk2(acc[i]);
                        atomicAdd(&s->invp[t + IOFF], v.x*v.x + v.y*v.y);
                    }
                }
                __syncthreads();    // ps complete before iter-2 power
            } else {
#pragma unroll
                for (int i = 0; i < 19; i++) {
                    int t = t0 + i;
                    if (t < TT) Eg[t] = upk2(acc[i]);
                }
            }
        }
    } // iterations
}

// ---------------------------------------------------------------------------
extern "C" void kernel_launch(void* const* d_in, const int* in_sizes, int n_in,
                              void* d_out, int out_size) {
    const float* re    = (const float*)d_in[0];
    const float* im    = (const float*)d_in[1];
    const int*   ilens = (const int*)d_in[2];
    float* out = (float*)d_out;

    cudaFuncSetAttribute(k_wpe, cudaFuncAttributeMaxDynamicSharedMemorySize,
                         (int)sizeof(WpeSmem));

    dim3 blk(32, 8);
    k_transpose_in<<<dim3((FF+31)/32, (TT+31)/32, BB*CC), blk>>>(re, im);
    k_wpe<<<NJOBS, NTHREADS, sizeof(WpeSmem)>>>();
    k_transpose_out<<<dim3((TT+31)/32, (FF+31)/32, BB*CC), blk>>>(out, ilens);
}

// round 15
// speedup vs baseline: 1.1119x; 1.0248x over previous
#include <cuda_runtime.h>
#include <math.h>

// Problem constants (fixed by setup_inputs)
#define BB 8
#define TT 600
#define CC 8
#define FF 257
#define NTAPS 5
#define NDELAY 3
#define KC 40           // NTAPS*CC
#define EPSV 1e-10f
#define NTHREADS 256
#define NJOBS (BB*FF)   // 2056
// valid frame count Tq = T - DELAY - TAPS + 1 = 593; u in [4, 597)

// Padded Y row: 8 leading zeros + 600 data + 10 trailing zeros = 618 float2.
// Row stride 618*8 B: 16B-aligned rows; bank offsets between rows = 20 mod 32
// -> all 8 channel rows on distinct banks.
#define TP 618
#define TOFF 8
#define IOFF 1          // invp values at [IOFF+t] so invp[IOFF+u0+3] is 16B-aligned

typedef unsigned long long u64;

// Scratch: Y and enhanced in (B,F,C,T) complex layout
__device__ float2 g_Y[(size_t)BB*FF*CC*TT];
__device__ float2 g_E[(size_t)BB*FF*CC*TT];

struct WpeSmem {
    float2 Y[CC][TP];          // 39552 B  (zero-padded both ends)
    float  invp[604];          //  2416 B  (weights during R/P; ps after)
    float2 R[KC][KC+1];        // 13120 B  (padded row; dinv lives in diag .y)
    float2 P[NTAPS][CC][CC];   //  2560 B  [k][e][d]
    float2 X[CC][KC];          //  2560 B  RHS panel, forward-solved in LDL
};                             // ~60208 B -> 3 CTAs/SM

// ---------------- packed f32x2 helpers (sm_103a FFMA2 path) ----------------
__device__ __forceinline__ u64 pk2(float lo, float hi) {
    u64 r; asm("mov.b64 %0, {%1, %2};" : "=l"(r) : "f"(lo), "f"(hi)); return r;
}
__device__ __forceinline__ float2 upk2(u64 v) {
    float2 r; asm("mov.b64 {%0, %1}, %2;" : "=f"(r.x), "=f"(r.y) : "l"(v)); return r;
}
__device__ __forceinline__ u64 fma2(u64 a, u64 b, u64 c) {
    u64 d; asm("fma.rn.f32x2 %0, %1, %2, %3;" : "=l"(d) : "l"(a), "l"(b), "l"(c)); return d;
}
__device__ __forceinline__ u64 mul2(u64 a, u64 b) {
    u64 d; asm("mul.rn.f32x2 %0, %1, %2;" : "=l"(d) : "l"(a), "l"(b)); return d;
}
// broadcast one lane of a packed pair into both lanes
__device__ __forceinline__ u64 bcast_lo(u64 v) {
    u64 r; asm("{\n\t.reg .f32 a,b;\n\tmov.b64 {a,b}, %1;\n\tmov.b64 %0, {a,a};\n\t}"
               : "=l"(r) : "l"(v)); return r;
}
__device__ __forceinline__ u64 bcast_hi(u64 v) {
    u64 r; asm("{\n\t.reg .f32 a,b;\n\tmov.b64 {a,b}, %1;\n\tmov.b64 %0, {b,b};\n\t}"
               : "=l"(r) : "l"(v)); return r;
}
__device__ __forceinline__ float2 shfl2(float2 v, int src) {
    float2 r;
    r.x = __shfl_sync(0xffffffffu, v.x, src);
    r.y = __shfl_sync(0xffffffffu, v.y, src);
    return r;
}
// load a float2 from smem directly as a u64 pack (operand-ready for fma2)
__device__ __forceinline__ u64 ldpk(const float2* p) {
    return *reinterpret_cast<const u64*>(p);
}

// ---------------------------------------------------------------------------
// Transpose in: (B,T,C,F) real+imag planes -> g_Y (B,F,C,T) float2
// ---------------------------------------------------------------------------
__global__ void k_transpose_in(const float* __restrict__ re,
                               const float* __restrict__ im) {
    __shared__ float2 tile[32][33];
    int bc = blockIdx.z;
    int b = bc / CC, c = bc % CC;
    int f0 = blockIdx.x * 32, t0 = blockIdx.y * 32;
    int tx = threadIdx.x, ty = threadIdx.y;
#pragma unroll
    for (int j = 0; j < 4; j++) {
        int t = t0 + ty + j*8, f = f0 + tx;
        if (t < TT && f < FF) {
            size_t idx = ((size_t)(b*TT + t)*CC + c)*FF + f;
            tile[ty + j*8][tx] = make_float2(re[idx], im[idx]);
        }
    }
    __syncthreads();
#pragma unroll
    for (int j = 0; j < 4; j++) {
        int f = f0 + ty + j*8, t = t0 + tx;
        if (t < TT && f < FF) {
            g_Y[((size_t)(b*FF + f)*CC + c)*TT + t] = tile[tx][ty + j*8];
        }
    }
}

// ---------------------------------------------------------------------------
// Transpose out: g_E (B,F,C,T) -> out real/imag planes (B,T,C,F), masked
// ---------------------------------------------------------------------------
__global__ void k_transpose_out(float* __restrict__ out,
                                const int* __restrict__ ilens) {
    __shared__ float2 tile[32][33];
    int bc = blockIdx.z;
    int b = bc / CC, c = bc % CC;
    int t0 = blockIdx.x * 32, f0 = blockIdx.y * 32;
    int tx = threadIdx.x, ty = threadIdx.y;
    int ilen = ilens[b];
    const size_t N = (size_t)BB*TT*CC*FF;
#pragma unroll
    for (int j = 0; j < 4; j++) {
        int f = f0 + ty + j*8, t = t0 + tx;
        if (t < TT && f < FF) {
            tile[ty + j*8][tx] = g_E[((size_t)(b*FF + f)*CC + c)*TT + t];
        }
    }
    __syncthreads();
#pragma unroll
    for (int j = 0; j < 4; j++) {
        int t = t0 + ty + j*8, f = f0 + tx;
        if (t < TT && f < FF) {
            float2 v = tile[tx][ty + j*8];
            if (t >= ilen) v = make_float2(0.f, 0.f);
            size_t idx = ((size_t)(b*TT + t)*CC + c)*FF + f;
            out[idx]     = v.x;
            out[N + idx] = v.y;
        }
    }
}

// ---------------------------------------------------------------------------
// Fused WPE: one CTA per (b,f). 2 iterations entirely in shared memory.
// ---------------------------------------------------------------------------
__global__ __launch_bounds__(NTHREADS, 3) void k_wpe() {
    extern __shared__ char smem_raw[];
    WpeSmem* s = (WpeSmem*)smem_raw;
    int bf = blockIdx.x;
    int tid = threadIdx.x;

    // Load Y rows into padded smem; zero the pads.
    const float2* Yg = g_Y + (size_t)bf * CC * TT;
#pragma unroll
    for (int c = 0; c < CC; c++)
        for (int t = tid; t < TT; t += NTHREADS)
            s->Y[c][t + TOFF] = Yg[c*TT + t];
    if (tid < CC * 18) {                 // 8 front + 10 back pads per row
        int c = tid / 18, p = tid % 18;
        int idx = (p < TOFF) ? p : (TT + p);   // 0..7 and 608..617
        s->Y[c][idx] = make_float2(0.f, 0.f);
    }
    __syncthreads();

    for (int it = 0; it < 2; it++) {
        // ---- power -> invp ----
        if (it == 0) {
            for (int t = tid; t < TT; t += NTHREADS) {
                float sum = 0.f;
#pragma unroll
                for (int c = 0; c < CC; c++) {
                    float2 y = s->Y[c][t + TOFF];
                    sum += y.x*y.x + y.y*y.y;
                }
                s->invp[t + IOFF] = 1.0f / fmaxf(sum * (1.0f / CC), EPSV);
            }
        } else {
            // invp currently holds ps (|E1|^2 sums); convert in place
            for (int t = tid; t < TT; t += NTHREADS)
                s->invp[t + IOFF] =
                    1.0f / fmaxf(s->invp[t + IOFF] * (1.0f / CC), EPSV);
        }
        __syncthreads();

        // ---- fused R + P accumulation, single pass over full u range ----
        // k-MAJOR thread map for R: pair = tid % 36, k = tid / 36, so lanes
        // within a warp share k (mostly) -> yd loads hit ONE time index
        // across bank-distinct rows = 1 smem wavefront (was 2-3).
        // R jobs: threads 0..179. P jobs: threads 192..255 (pair (d,e)).
        if (tid < 180) {
            int pair = tid % 36, k = tid / 36;
            int e = 0;
            while ((e+1)*(e+2)/2 <= pair) e++;
            int d = pair - e*(e+1)/2;            // d <= e
            u64 accA[NTAPS], accB[NTAPS];
#pragma unroll
            for (int l = 0; l < NTAPS; l++) { accA[l] = 0ull; accB[l] = 0ull; }
            u64 pe[12];                          // pe[c] = Ye[u0-4+c] pack
#pragma unroll
            for (int c = 0; c < 4; c += 2) {
                ulonglong2 q = *reinterpret_cast<const ulonglong2*>(&s->Y[e][c + TOFF]);
                pe[c] = q.x; pe[c+1] = q.y;
            }

            for (int u0 = 4; u0 < 596; u0 += 8) {
                float4 w4a = *reinterpret_cast<const float4*>(&s->invp[IOFF + u0 + 3]);
                float4 w4b = *reinterpret_cast<const float4*>(&s->invp[IOFF + u0 + 7]);
#pragma unroll
                for (int c = 0; c < 8; c += 2) {
                    ulonglong2 q = *reinterpret_cast<const ulonglong2*>(&s->Y[e][u0 + c + TOFF]);
                    pe[4 + c] = q.x; pe[5 + c] = q.y;
                }
                float wj[8] = {w4a.x, w4a.y, w4a.z, w4a.w,
                               w4b.x, w4b.y, w4b.z, w4b.w};
#pragma unroll
                for (int j = 0; j < 8; j++) {
                    float2 yd = s->Y[d][u0 + j - k + TOFF];
                    u64 s2 = mul2(pk2(wj[j], wj[j]), pk2(yd.x, yd.y));
                    u64 aw = bcast_lo(s2);
                    u64 bw = bcast_hi(s2);
#pragma unroll
                    for (int l = 0; l < NTAPS; l++) {
                        accA[l] = fma2(aw, pe[j + 4 - l], accA[l]);
                        accB[l] = fma2(bw, pe[j + 4 - l], accB[l]);
                    }
                }
#pragma unroll
                for (int c = 0; c < 4; c++) pe[c] = pe[8 + c];
            }
            {   // remainder u = 596 (pe[0..3] = Ye[592..595])
                pe[4] = ldpk(&s->Y[e][596 + TOFF]);
                float2 yd = s->Y[d][596 - k + TOFF];
                float w = s->invp[IOFF + 599];
                u64 s2 = mul2(pk2(w, w), pk2(yd.x, yd.y));
                u64 aw = bcast_lo(s2);
                u64 bw = bcast_hi(s2);
#pragma unroll
                for (int l = 0; l < NTAPS; l++) {
                    accA[l] = fma2(aw, pe[4 - l], accA[l]);
                    accB[l] = fma2(bw, pe[4 - l], accB[l]);
                }
            }
#pragma unroll
            for (int l = 0; l < NTAPS; l++) {
                float2 A = upk2(accA[l]), B = upk2(accB[l]);
                float2 v = make_float2(A.x + B.y, A.y - B.x);
                s->R[k*CC + d][l*CC + e] = v;
                if (d < e)
                    s->R[l*CC + e][k*CC + d] = make_float2(v.x, -v.y);
            }
        } else if (tid >= 192) {
            int pair = tid - 192;
            int d = pair & 7, e = pair >> 3;
            u64 accA[NTAPS], accB[NTAPS];
#pragma unroll
            for (int k = 0; k < NTAPS; k++) { accA[k] = 0ull; accB[k] = 0ull; }
            u64 pdw[12];                         // pdw[c] = Yd[u0-4+c] pack
#pragma unroll
            for (int c = 0; c < 4; c += 2) {
                ulonglong2 q = *reinterpret_cast<const ulonglong2*>(&s->Y[d][c + TOFF]);
                pdw[c] = q.x; pdw[c+1] = q.y;
            }

            for (int u0 = 4; u0 < 596; u0 += 8) {
                float4 w4a = *reinterpret_cast<const float4*>(&s->invp[IOFF + u0 + 3]);
                float4 w4b = *reinterpret_cast<const float4*>(&s->invp[IOFF + u0 + 7]);
#pragma unroll
                for (int c = 0; c < 8; c += 2) {
                    ulonglong2 q = *reinterpret_cast<const ulonglong2*>(&s->Y[d][u0 + c + TOFF]);
                    pdw[4 + c] = q.x; pdw[5 + c] = q.y;
                }
                float wj[8] = {w4a.x, w4a.y, w4a.z, w4a.w,
                               w4b.x, w4b.y, w4b.z, w4b.w};
#pragma unroll
                for (int j = 0; j < 8; j++) {
                    float2 ye = s->Y[e][u0 + j + 3 + TOFF];
                    u64 sv = mul2(pk2(wj[j], wj[j]), pk2(ye.x, ye.y));
                    u64 svl = bcast_lo(sv);
                    u64 svh = bcast_hi(sv);
#pragma unroll
                    for (int k = 0; k < NTAPS; k++) {
                        accA[k] = fma2(pdw[j + 4 - k], svl, accA[k]);
                        accB[k] = fma2(pdw[j + 4 - k], svh, accB[k]);
                    }
                }
#pragma unroll
                for (int c = 0; c < 4; c++) pdw[c] = pdw[8 + c];
            }
            {   // remainder u = 596 (pdw[0..3] = Yd[592..595])
                pdw[4] = ldpk(&s->Y[d][596 + TOFF]);
                float2 ye = s->Y[e][599 + TOFF];
                float w = s->invp[IOFF + 599];
                u64 sv = mul2(pk2(w, w), pk2(ye.x, ye.y));
                u64 svl = bcast_lo(sv);
                u64 svh = bcast_hi(sv);
#pragma unroll
                for (int k = 0; k < NTAPS; k++) {
                    accA[k] = fma2(pdw[4 - k], svl, accA[k]);
                    accB[k] = fma2(pdw[4 - k], svh, accB[k]);
                }
            }
#pragma unroll
            for (int k = 0; k < NTAPS; k++) {
                float2 A = upk2(accA[k]), B = upk2(accB[k]);
                // re = ydx*svx + ydy*svy ; im = ydx*svy - ydy*svx
                s->P[k][e][d] = make_float2(A.x + B.y, B.x - A.y);
            }
        }
        __syncthreads();

        // ---- weights dead: repurpose invp as ps accumulator (zero it);
        //      regularize R diag; stage RHS panel X[e][i] = P (i=(k*8+d)).
        //      All covered by LDL's first barrier. ----
        for (int t = tid; t < TT; t += NTHREADS) s->invp[t + IOFF] = 0.f;
        if (tid < KC) s->R[tid][tid].x += EPSV;
        {
            int lane = tid & 31, e = tid >> 5;
            for (int i = lane; i < KC; i += 32)
                s->X[e][i] = s->P[i>>3][e][i&7];
        }

        // ---- in-place LDL^H of R with fused forward solve of the 8 RHS:
        //      one barrier per column; dinv -> R[j][j].y. ----
        for (int j = 0; j < KC; j++) {
            __syncthreads();                 // column j fully updated
            float djj = s->R[j][j].x;        // broadcast read
            float dinv = 1.0f / fmaxf(djj, 1e-30f);
            if (tid == 0) s->R[j][j].y = dinv;
            int w = tid >> 5;                // 0..7 (l-stride / rhs column)
            float2 Xj = s->X[w][j];
            for (int i = j + 1 + (tid & 31); i < KC; i += 32) {
                float2 Aij = s->R[i][j];
                float2 Aw = make_float2(Aij.x * dinv, Aij.y * dinv);
                for (int l = j + 1 + w; l <= i; l += 8) {
                    float2 Alj = s->R[l][j];
                    s->R[i][l].x -= Aw.x*Alj.x + Aw.y*Alj.y;
                    s->R[i][l].y -= Aw.y*Alj.x - Aw.x*Alj.y;
                }
                // fused forward solve: rhs column w, row i
                s->X[w][i].x -= Aw.x*Xj.x - Aw.y*Xj.y;
                s->X[w][i].y -= Aw.x*Xj.y + Aw.y*Xj.x;
            }
        }
        __syncthreads();

        // ---- backward solve in registers: warp e solves channel e.
        //      Result x0/x1 stays in registers: G is carried into reverb
        //      via shfl (no G smem array, no extra barrier). ----
        float2 x0, x1;
        {
            int lane = tid & 31, e = tid >> 5;
            x0 = s->X[e][lane];
            x1 = (lane < 8) ? s->X[e][lane + 32] : make_float2(0.f, 0.f);
            float dinv0 = s->R[lane][lane].y;
            float dinv1 = (lane < 8) ? s->R[lane+32][lane+32].y : 0.f;

            // z = D^{-1} y
            x0.x *= dinv0; x0.y *= dinv0;
            x1.x *= dinv1; x1.y *= dinv1;
            // backward: L^H x = z ;  x_i -= dinv_i * conj(A[j][i]) * x_j, i<j
            for (int j = KC - 1; j >= 1; j--) {
                int src = j & 31;
                float2 xj = (j < 32) ? shfl2(x0, src) : shfl2(x1, src);
                if (lane < j) {
                    float2 A = s->R[j][lane];
                    x0.x -= dinv0 * (A.x*xj.x + A.y*xj.y);
                    x0.y -= dinv0 * (A.x*xj.y - A.y*xj.x);
                }
                if (lane < 8 && lane + 32 < j) {
                    float2 A = s->R[j][lane+32];
                    x1.x -= dinv1 * (A.x*xj.x + A.y*xj.y);
                    x1.y -= dinv1 * (A.x*xj.y - A.y*xj.x);
                }
            }
            // x0 holds G entries (p = lane>>3 in 0..3, d = lane&7); x1: p=4, d=lane
        }
        // NO barrier: G travels in-register within each warp.

        // ---- reverb: E[e][t] = Y[e][t] - sum_{p,d} G[p][d][e]*Y[d][t-3-p]
        // single-pass 19 frames/lane; padded Y -> NO load guards.
        // g values fetched from the solve result via warp shuffle.
        // iter-1: accumulate |E|^2 into invp (ps). iter-2: store E to g_E.
        {
            int lane = tid & 31, e = tid >> 5;
            int t0 = lane * 19;
            float2* Eg = g_E + ((size_t)bf * CC + e) * TT;
            u64 acc[19];
#pragma unroll
            for (int i = 0; i < 19; i++)
                acc[i] = ldpk(&s->Y[e][t0 + i + TOFF]);   // pad reads give zeros
#pragma unroll
            for (int d = 0; d < CC; d++) {
                u64 gxn[NTAPS], gys[NTAPS];
#pragma unroll
                for (int p = 0; p < NTAPS; p++) {
                    float2 g = (p < 4) ? shfl2(x0, p*8 + d) : shfl2(x1, d);
                    gxn[p] = pk2(-g.x, -g.x);
                    gys[p] = pk2(g.y, -g.y);
                }
                u64 w[NTAPS], ws[NTAPS];
#pragma unroll
                for (int p = 0; p < NTAPS-1; p++) {
                    float2 y = s->Y[d][t0 - 4 - p + TOFF];  // pad-safe
                    w[p]  = pk2(y.x, y.y);
                    ws[p] = pk2(y.y, y.x);
                }
                w[NTAPS-1] = ws[NTAPS-1] = 0ull;
#pragma unroll
                for (int i = 0; i < 19; i++) {
#pragma unroll
                    for (int p = NTAPS-1; p > 0; p--) { w[p]=w[p-1]; ws[p]=ws[p-1]; }
                    float2 y = s->Y[d][t0 + i - 3 + TOFF];  // pad-safe both ends
                    w[0]  = pk2(y.x, y.y);
                    ws[0] = pk2(y.y, y.x);
#pragma unroll
                    for (int p = 0; p < NTAPS; p++) {
                        acc[i] = fma2(gxn[p], w[p],  acc[i]);
                        acc[i] = fma2(gys[p], ws[p], acc[i]);
                    }
                }
            }
            if (it == 0) {
#pragma unroll
                for (int i = 0; i < 19; i++) {
                    int t = t0 + i;
                    if (t < TT) {
                        float2 v = upk2(acc[i]);
                        atomicAdd(&s->invp[t + IOFF], v.x*v.x + v.y*v.y);
                    }
                }
                __syncthreads();    // ps complete before iter-2 power
            } else {
#pragma unroll
                for (int i = 0; i < 19; i++) {
                    int t = t0 + i;
                    if (t < TT) Eg[t] = upk2(acc[i]);
                }
            }
        }
    } // iterations
}

// ---------------------------------------------------------------------------
extern "C" void kernel_launch(void* const* d_in, const int* in_sizes, int n_in,
                              void* d_out, int out_size) {
    const float* re    = (const float*)d_in[0];
    const float* im    = (const float*)d_in[1];
    const int*   ilens = (const int*)d_in[2];
    float* out = (float*)d_out;

    cudaFuncSetAttribute(k_wpe, cudaFuncAttributeMaxDynamicSharedMemorySize,
                         (int)sizeof(WpeSmem));

    dim3 blk(32, 8);
    k_transpose_in<<<dim3((FF+31)/32, (TT+31)/32, BB*CC), blk>>>(re, im);
    k_wpe<<<NJOBS, NTHREADS, sizeof(WpeSmem)>>>();
    k_transpose_out<<<dim3((TT+31)/32, (FF+31)/32, BB*CC), blk>>>(out, ilens);
}